// round 1
// baseline (speedup 1.0000x reference)
#include <cuda_runtime.h>
#include <math.h>
#include <stdint.h>

#define NN 50000
#define NE 640000
#define RR 8
#define DD 128
#define NRSEG (NN*RR)
#define NBLK ((NRSEG + 1023)/1024)

// ---------------- scratch (device globals; no allocations allowed) ----------
__device__ int   g_cnt[NRSEG];
__device__ int   g_off[NRSEG];
__device__ int   g_cur[NRSEG];
__device__ int   g_bsum[NBLK];
__device__ int   g_srcs[NE];
__device__ float g_h[NN*DD];

// ---------------- CSR build: histogram -> scan -> scatter -------------------
__global__ void k_zero() {
    int i = blockIdx.x*blockDim.x + threadIdx.x;
    if (i < NRSEG) g_cnt[i] = 0;
}

__global__ void k_hist(const int* __restrict__ dst, const int* __restrict__ typ) {
    int e = blockIdx.x*blockDim.x + threadIdx.x;
    if (e < NE) atomicAdd(&g_cnt[dst[e]*RR + typ[e]], 1);
}

__global__ void k_scan1() {
    __shared__ int s[1024];
    int tid = threadIdx.x;
    int i = blockIdx.x*1024 + tid;
    int v = (i < NRSEG) ? g_cnt[i] : 0;
    s[tid] = v; __syncthreads();
    for (int d = 1; d < 1024; d <<= 1) {
        int t = (tid >= d) ? s[tid-d] : 0;
        __syncthreads();
        s[tid] += t;
        __syncthreads();
    }
    if (i < NRSEG) g_off[i] = s[tid] - v;   // exclusive within block
    if (tid == 1023) g_bsum[blockIdx.x] = s[1023];
}

__global__ void k_scan2() {
    __shared__ int s[512];
    int tid = threadIdx.x;
    int v = (tid < NBLK) ? g_bsum[tid] : 0;
    s[tid] = v; __syncthreads();
    for (int d = 1; d < 512; d <<= 1) {
        int t = (tid >= d) ? s[tid-d] : 0;
        __syncthreads();
        s[tid] += t;
        __syncthreads();
    }
    if (tid < NBLK) g_bsum[tid] = s[tid] - v;  // exclusive block sums
}

__global__ void k_scan3() {
    int i = blockIdx.x*blockDim.x + threadIdx.x;
    if (i < NRSEG) {
        int o = g_off[i] + g_bsum[i >> 10];
        g_off[i] = o;
        g_cur[i] = o;
    }
}

__global__ void k_scatter(const int* __restrict__ src, const int* __restrict__ dst,
                          const int* __restrict__ typ) {
    int e = blockIdx.x*blockDim.x + threadIdx.x;
    if (e < NE) {
        int seg = dst[e]*RR + typ[e];
        int pos = atomicAdd(&g_cur[seg], 1);
        g_srcs[pos] = src[e];
    }
}

// ---------------- fused aggregate + GEMM layer ------------------------------
__device__ __forceinline__ uint32_t f2tf(float x) {
    uint32_t r;
    asm("cvt.rna.tf32.f32 %0, %1;" : "=r"(r) : "f"(x));
    return r;
}

__device__ __forceinline__ void mma_tf32(float& c0, float& c1, float& c2, float& c3,
                                         uint32_t a0, uint32_t a1, uint32_t a2, uint32_t a3,
                                         uint32_t b0, uint32_t b1) {
    asm volatile(
        "mma.sync.aligned.m16n8k8.row.col.f32.tf32.tf32.f32 "
        "{%0,%1,%2,%3},{%4,%5,%6,%7},{%8,%9},{%0,%1,%2,%3};"
        : "+f"(c0), "+f"(c1), "+f"(c2), "+f"(c3)
        : "r"(a0), "r"(a1), "r"(a2), "r"(a3), "r"(b0), "r"(b1));
}

// CTA = 128 nodes x O outputs. For each of 9 chunks (8 relations + root):
//   phase A: build mean tile [128 x 128] in smem (CSR gather, x resident in L2)
//   phase B: acc += A_chunk @ W_chunk   (tf32 mma.sync, fp32 accum)
template<int O, bool SIG>
__global__ void k_layer(const float* __restrict__ in,
                        const float* __restrict__ Wrel,
                        const float* __restrict__ Wroot,
                        const float* __restrict__ bias,
                        float* __restrict__ out) {
    constexpr int TM = 128;
    constexpr int AP = DD + 4;   // pad: conflict-free A-frag loads
    constexpr int BP = O + 4;
    extern __shared__ float smem[];
    float* sA = smem;              // TM x AP
    float* sB = smem + TM*AP;      // DD x BP

    const int tid  = threadIdx.x;
    const int lane = tid & 31;
    const int wid  = tid >> 5;
    const int tile = blockIdx.x * TM;

    float acc[O/8][4];
    #pragma unroll
    for (int n8 = 0; n8 < O/8; ++n8) {
        acc[n8][0] = 0.f; acc[n8][1] = 0.f; acc[n8][2] = 0.f; acc[n8][3] = 0.f;
    }

    const int g  = lane >> 2;
    const int tg = lane & 3;

    for (int r = 0; r < RR + 1; ++r) {
        // ---- phase A: build tile rows (each warp owns rows wid, wid+8, ...)
        for (int i = wid; i < TM; i += 8) {
            int node = tile + i;
            float4 v = make_float4(0.f, 0.f, 0.f, 0.f);
            if (node < NN) {
                if (r < RR) {
                    int seg   = node*RR + r;
                    int start = g_off[seg];
                    int c     = g_cnt[seg];
                    for (int base = 0; base < c; base += 32) {
                        int m = min(c - base, 32);
                        int s = (lane < m) ? g_srcs[start + base + lane] : 0;
                        for (int j = 0; j < m; ++j) {
                            int src = __shfl_sync(0xffffffffu, s, j);
                            const float4 xv = *reinterpret_cast<const float4*>(
                                in + (size_t)src*DD + lane*4);
                            v.x += xv.x; v.y += xv.y; v.z += xv.z; v.w += xv.w;
                        }
                    }
                    if (c > 0) {
                        float inv = 1.f / (float)c;
                        v.x *= inv; v.y *= inv; v.z *= inv; v.w *= inv;
                    }
                } else {
                    v = *reinterpret_cast<const float4*>(in + (size_t)node*DD + lane*4);
                }
            }
            float4 t;
            t.x = __uint_as_float(f2tf(v.x));
            t.y = __uint_as_float(f2tf(v.y));
            t.z = __uint_as_float(f2tf(v.z));
            t.w = __uint_as_float(f2tf(v.w));
            *reinterpret_cast<float4*>(&sA[i*AP + lane*4]) = t;
        }
        // ---- load W chunk [DD x O] (L2-broadcast across CTAs)
        {
            const float* Wp = (r < RR) ? (Wrel + (size_t)r*DD*O) : Wroot;
            for (int idx = tid; idx < DD*O; idx += blockDim.x) {
                int k = idx / O, n = idx - k*O;
                sB[k*BP + n] = __uint_as_float(f2tf(Wp[idx]));
            }
        }
        __syncthreads();

        // ---- phase B: tf32 MMA, warp owns 16 rows x O cols
        const int mrow = wid * 16;
        #pragma unroll
        for (int k8 = 0; k8 < DD/8; ++k8) {
            uint32_t a0 = __float_as_uint(sA[(mrow + g    )*AP + k8*8 + tg    ]);
            uint32_t a1 = __float_as_uint(sA[(mrow + g + 8)*AP + k8*8 + tg    ]);
            uint32_t a2 = __float_as_uint(sA[(mrow + g    )*AP + k8*8 + tg + 4]);
            uint32_t a3 = __float_as_uint(sA[(mrow + g + 8)*AP + k8*8 + tg + 4]);
            #pragma unroll
            for (int n8 = 0; n8 < O/8; ++n8) {
                uint32_t b0 = __float_as_uint(sB[(k8*8 + tg    )*BP + n8*8 + g]);
                uint32_t b1 = __float_as_uint(sB[(k8*8 + tg + 4)*BP + n8*8 + g]);
                mma_tf32(acc[n8][0], acc[n8][1], acc[n8][2], acc[n8][3],
                         a0, a1, a2, a3, b0, b1);
            }
        }
        __syncthreads();
    }

    // ---- epilogue: bias (+ sigmoid), write out
    const int r0 = tile + wid*16 + g;
    const int r1 = r0 + 8;
    #pragma unroll
    for (int n8 = 0; n8 < O/8; ++n8) {
        int c0 = n8*8 + 2*tg;
        int c1 = c0 + 1;
        float bz0 = bias[c0], bz1 = bias[c1];
        float v00 = acc[n8][0] + bz0;
        float v01 = acc[n8][1] + bz1;
        float v10 = acc[n8][2] + bz0;
        float v11 = acc[n8][3] + bz1;
        if (SIG) {
            v00 = 1.f/(1.f + expf(-v00));
            v01 = 1.f/(1.f + expf(-v01));
            v10 = 1.f/(1.f + expf(-v10));
            v11 = 1.f/(1.f + expf(-v11));
        }
        if (r0 < NN) { out[(size_t)r0*O + c0] = v00; out[(size_t)r0*O + c1] = v01; }
        if (r1 < NN) { out[(size_t)r1*O + c0] = v10; out[(size_t)r1*O + c1] = v11; }
    }
}

// ---------------- launch ----------------------------------------------------
extern "C" void kernel_launch(void* const* d_in, const int* in_sizes, int n_in,
                              void* d_out, int out_size) {
    const float* x    = (const float*)d_in[0];
    const int*   esrc = (const int*)  d_in[1];
    const int*   edst = (const int*)  d_in[2];
    const int*   etyp = (const int*)  d_in[3];
    const float* W1   = (const float*)d_in[4];
    const float* r1   = (const float*)d_in[5];
    const float* b1   = (const float*)d_in[6];
    const float* W2   = (const float*)d_in[7];
    const float* r2   = (const float*)d_in[8];
    const float* b2   = (const float*)d_in[9];
    float* out = (float*)d_out;

    constexpr int SMEM_L1 = (128*(DD+4) + DD*(128+4)) * 4;  // 135168 B
    constexpr int SMEM_L2 = (128*(DD+4) + DD*( 64+4)) * 4;  // 102400 B
    cudaFuncSetAttribute(k_layer<128,false>, cudaFuncAttributeMaxDynamicSharedMemorySize, SMEM_L1);
    cudaFuncSetAttribute(k_layer< 64,true >, cudaFuncAttributeMaxDynamicSharedMemorySize, SMEM_L2);

    void* hp = nullptr;
    cudaGetSymbolAddress(&hp, g_h);
    float* h = (float*)hp;

    k_zero   <<<(NRSEG+255)/256, 256>>>();
    k_hist   <<<(NE+255)/256,    256>>>(edst, etyp);
    k_scan1  <<<NBLK,           1024>>>();
    k_scan2  <<<1,               512>>>();
    k_scan3  <<<(NRSEG+255)/256, 256>>>();
    k_scatter<<<(NE+255)/256,    256>>>(esrc, edst, etyp);

    k_layer<128,false><<<(NN+127)/128, 256, SMEM_L1>>>(x, W1, r1, b1, h);
    k_layer< 64,true ><<<(NN+127)/128, 256, SMEM_L2>>>(h, W2, r2, b2, out);
}

// round 2
// speedup vs baseline: 1.7515x; 1.7515x over previous
#include <cuda_runtime.h>
#include <math.h>
#include <stdint.h>

#define NN 50000
#define NE 640000
#define RR 8
#define DD 128
#define NRSEG (NN*RR)
#define NBLK ((NRSEG + 1023)/1024)

// ---------------- scratch (device globals; no allocations allowed) ----------
__device__ int   g_cnt[NRSEG];
__device__ int   g_off[NRSEG];
__device__ int   g_cur[NRSEG];
__device__ int   g_bsum[NBLK];
__device__ int   g_srcs[NE];
__device__ float g_h[NN*DD];
__device__ float g_Wt1[(RR+1)*DD*DD];   // [chunk][n][k], chunk 8 = root
__device__ float g_Wt2[(RR+1)*64*DD];

// ---------------- CSR build: histogram -> scan -> scatter -------------------
__global__ void k_zero() {
    int i = blockIdx.x*blockDim.x + threadIdx.x;
    if (i < NRSEG) g_cnt[i] = 0;
}

__global__ void k_hist(const int* __restrict__ dst, const int* __restrict__ typ) {
    int e = blockIdx.x*blockDim.x + threadIdx.x;
    if (e < NE) atomicAdd(&g_cnt[dst[e]*RR + typ[e]], 1);
}

__global__ void k_scan1() {
    __shared__ int s[1024];
    int tid = threadIdx.x;
    int i = blockIdx.x*1024 + tid;
    int v = (i < NRSEG) ? g_cnt[i] : 0;
    s[tid] = v; __syncthreads();
    for (int d = 1; d < 1024; d <<= 1) {
        int t = (tid >= d) ? s[tid-d] : 0;
        __syncthreads();
        s[tid] += t;
        __syncthreads();
    }
    if (i < NRSEG) g_off[i] = s[tid] - v;
    if (tid == 1023) g_bsum[blockIdx.x] = s[1023];
}

__global__ void k_scan2() {
    __shared__ int s[512];
    int tid = threadIdx.x;
    int v = (tid < NBLK) ? g_bsum[tid] : 0;
    s[tid] = v; __syncthreads();
    for (int d = 1; d < 512; d <<= 1) {
        int t = (tid >= d) ? s[tid-d] : 0;
        __syncthreads();
        s[tid] += t;
        __syncthreads();
    }
    if (tid < NBLK) g_bsum[tid] = s[tid] - v;
}

__global__ void k_scan3() {
    int i = blockIdx.x*blockDim.x + threadIdx.x;
    if (i < NRSEG) {
        int o = g_off[i] + g_bsum[i >> 10];
        g_off[i] = o;
        g_cur[i] = o;
    }
}

__global__ void k_scatter(const int* __restrict__ src, const int* __restrict__ dst,
                          const int* __restrict__ typ) {
    int e = blockIdx.x*blockDim.x + threadIdx.x;
    if (e < NE) {
        int seg = dst[e]*RR + typ[e];
        int pos = atomicAdd(&g_cur[seg], 1);
        g_srcs[pos] = src[e];
    }
}

// ---------------- weight transpose: Wt[chunk][n][k] -------------------------
__global__ void k_transpose(const float* __restrict__ W, const float* __restrict__ root,
                            float* __restrict__ out, int O) {
    int idx = blockIdx.x*blockDim.x + threadIdx.x;
    int total = (RR+1)*O*DD;
    if (idx >= total) return;
    int chunk = idx / (O*DD);
    int rem   = idx - chunk*(O*DD);
    int n = rem / DD, k = rem - n*DD;
    float v = (chunk < RR) ? W[(size_t)chunk*DD*O + (size_t)k*O + n]
                           : root[(size_t)k*O + n];
    out[idx] = v;
}

// ---------------- fused aggregate + GEMM layer ------------------------------
__device__ __forceinline__ uint32_t f2tf(float x) {
    uint32_t r;
    asm("cvt.rna.tf32.f32 %0, %1;" : "=r"(r) : "f"(x));
    return r;
}

__device__ __forceinline__ void mma_tf32(float& c0, float& c1, float& c2, float& c3,
                                         uint32_t a0, uint32_t a1, uint32_t a2, uint32_t a3,
                                         uint32_t b0, uint32_t b1) {
    asm volatile(
        "mma.sync.aligned.m16n8k8.row.col.f32.tf32.tf32.f32 "
        "{%0,%1,%2,%3},{%4,%5,%6,%7},{%8,%9},{%0,%1,%2,%3};"
        : "+f"(c0), "+f"(c1), "+f"(c2), "+f"(c3)
        : "r"(a0), "r"(a1), "r"(a2), "r"(a3), "r"(b0), "r"(b1));
}

// CTA = 128 nodes x O outputs. For each of 9 chunks (8 relations + root):
//   phase A: build mean tile [128 x 128] in smem (register-batched gather, MLP 8)
//   phase B: acc += A_chunk @ W_chunk   (tf32 mma.sync, fp32 accum)
template<int O, bool SIG>
__global__ void __launch_bounds__(256, 1)
k_layer(const float* __restrict__ in,
        const float* __restrict__ Wt,     // [9][O][DD] pre-transposed
        const float* __restrict__ bias,
        float* __restrict__ out) {
    constexpr int TM = 128;
    constexpr int AP = DD + 4;
    constexpr int KP = DD + 4;
    constexpr int CAP = 6144;     // staged edge capacity per tile

    extern __shared__ char smem_raw[];
    float* sA   = (float*)smem_raw;             // TM x AP
    float* sBT  = sA + TM*AP;                   // O x KP  (n-major, transposed)
    int*   s_off = (int*)(sBT + O*KP);          // TM*RR
    int*   s_cnt = s_off + TM*RR;               // TM*RR
    int*   s_src = s_cnt + TM*RR;               // CAP

    const int tid  = threadIdx.x;
    const int lane = tid & 31;
    const int wid  = tid >> 5;
    const int tile = blockIdx.x * TM;
    const int segbase = tile * RR;

    // ---- cooperative metadata load (contiguous in CSR arrays)
    for (int t = tid; t < TM*RR; t += 256) {
        int gi = segbase + t;
        int c = 0, o = 0;
        if (gi < NRSEG) { c = g_cnt[gi]; o = g_off[gi]; }
        s_cnt[t] = c; s_off[t] = o;
    }
    __syncthreads();

    // ---- stage the tile's edge slice (contiguous in g_srcs)
    const int nseg = min(TM*RR, NRSEG - segbase);
    const int ebase = s_off[0];
    const int eend  = s_off[nseg-1] + s_cnt[nseg-1];
    const int ecnt  = eend - ebase;
    const bool use_s = (ecnt <= CAP);
    if (use_s) {
        for (int t = tid; t < ecnt; t += 256) s_src[t] = g_srcs[ebase + t];
    }
    __syncthreads();

    float acc[O/8][4];
    #pragma unroll
    for (int n8 = 0; n8 < O/8; ++n8) {
        acc[n8][0] = 0.f; acc[n8][1] = 0.f; acc[n8][2] = 0.f; acc[n8][3] = 0.f;
    }

    const int g  = lane >> 2;
    const int tg = lane & 3;
    const int rbase = wid * 16;    // warp owns rows [rbase, rbase+16)

    for (int r = 0; r < RR + 1; ++r) {
        // ================= phase A =================
        if (r < RR) {
            #pragma unroll 1
            for (int half = 0; half < 2; ++half) {
                const int rb = rbase + half*8;
                float4 v[8];
                int off8[8], cnt8[8];
                int maxc = 0;
                #pragma unroll
                for (int ii = 0; ii < 8; ++ii) {
                    int m = (rb + ii)*RR + r;
                    cnt8[ii] = s_cnt[m];
                    off8[ii] = s_off[m] - (use_s ? ebase : 0);
                    v[ii] = make_float4(0.f, 0.f, 0.f, 0.f);
                    maxc = max(maxc, cnt8[ii]);
                }
                // edge-slot loop: 8 independent gathers in flight per step
                for (int j = 0; j < maxc; ++j) {
                    #pragma unroll
                    for (int ii = 0; ii < 8; ++ii) {
                        if (j < cnt8[ii]) {
                            int src = use_s ? s_src[off8[ii] + j]
                                            : g_srcs[off8[ii] + j];
                            const float4 xv = *reinterpret_cast<const float4*>(
                                in + (size_t)src*DD + (lane << 2));
                            v[ii].x += xv.x; v[ii].y += xv.y;
                            v[ii].z += xv.z; v[ii].w += xv.w;
                        }
                    }
                }
                #pragma unroll
                for (int ii = 0; ii < 8; ++ii) {
                    float s = (cnt8[ii] > 0) ? (1.f / (float)cnt8[ii]) : 0.f;
                    float4 t;
                    t.x = __uint_as_float(f2tf(v[ii].x * s));
                    t.y = __uint_as_float(f2tf(v[ii].y * s));
                    t.z = __uint_as_float(f2tf(v[ii].z * s));
                    t.w = __uint_as_float(f2tf(v[ii].w * s));
                    *reinterpret_cast<float4*>(&sA[(rb + ii)*AP + (lane << 2)]) = t;
                }
            }
        } else {
            // root chunk: direct copy of input tile
            #pragma unroll
            for (int ii = 0; ii < 16; ++ii) {
                int node = tile + rbase + ii;
                float4 t = make_float4(0.f, 0.f, 0.f, 0.f);
                if (node < NN) {
                    const float4 xv = *reinterpret_cast<const float4*>(
                        in + (size_t)node*DD + (lane << 2));
                    t.x = __uint_as_float(f2tf(xv.x));
                    t.y = __uint_as_float(f2tf(xv.y));
                    t.z = __uint_as_float(f2tf(xv.z));
                    t.w = __uint_as_float(f2tf(xv.w));
                }
                *reinterpret_cast<float4*>(&sA[(rbase + ii)*AP + (lane << 2)]) = t;
            }
        }
        // ---- load W chunk (pre-transposed: coalesced LDG, conflict-free STS)
        {
            const float* Wp = Wt + (size_t)r*O*DD;
            for (int idx = tid; idx < O*DD; idx += 256) {
                int n = idx >> 7, k = idx & (DD-1);
                sBT[n*KP + k] = __uint_as_float(f2tf(Wp[idx]));
            }
        }
        __syncthreads();

        // ================= phase B: tf32 MMA =================
        const int mrow = rbase;
        #pragma unroll
        for (int k8 = 0; k8 < DD/8; ++k8) {
            uint32_t a0 = __float_as_uint(sA[(mrow + g    )*AP + k8*8 + tg    ]);
            uint32_t a1 = __float_as_uint(sA[(mrow + g + 8)*AP + k8*8 + tg    ]);
            uint32_t a2 = __float_as_uint(sA[(mrow + g    )*AP + k8*8 + tg + 4]);
            uint32_t a3 = __float_as_uint(sA[(mrow + g + 8)*AP + k8*8 + tg + 4]);
            #pragma unroll
            for (int n8 = 0; n8 < O/8; ++n8) {
                uint32_t b0 = __float_as_uint(sBT[(n8*8 + g)*KP + k8*8 + tg    ]);
                uint32_t b1 = __float_as_uint(sBT[(n8*8 + g)*KP + k8*8 + tg + 4]);
                mma_tf32(acc[n8][0], acc[n8][1], acc[n8][2], acc[n8][3],
                         a0, a1, a2, a3, b0, b1);
            }
        }
        __syncthreads();
    }

    // ---- epilogue: bias (+ sigmoid), write out
    const int r0 = tile + rbase + g;
    const int r1 = r0 + 8;
    #pragma unroll
    for (int n8 = 0; n8 < O/8; ++n8) {
        int c0 = n8*8 + 2*tg;
        int c1 = c0 + 1;
        float bz0 = bias[c0], bz1 = bias[c1];
        float v00 = acc[n8][0] + bz0;
        float v01 = acc[n8][1] + bz1;
        float v10 = acc[n8][2] + bz0;
        float v11 = acc[n8][3] + bz1;
        if (SIG) {
            v00 = 1.f/(1.f + __expf(-v00));
            v01 = 1.f/(1.f + __expf(-v01));
            v10 = 1.f/(1.f + __expf(-v10));
            v11 = 1.f/(1.f + __expf(-v11));
        }
        if (r0 < NN) { out[(size_t)r0*O + c0] = v00; out[(size_t)r0*O + c1] = v01; }
        if (r1 < NN) { out[(size_t)r1*O + c0] = v10; out[(size_t)r1*O + c1] = v11; }
    }
}

// ---------------- launch ----------------------------------------------------
extern "C" void kernel_launch(void* const* d_in, const int* in_sizes, int n_in,
                              void* d_out, int out_size) {
    const float* x    = (const float*)d_in[0];
    const int*   esrc = (const int*)  d_in[1];
    const int*   edst = (const int*)  d_in[2];
    const int*   etyp = (const int*)  d_in[3];
    const float* W1   = (const float*)d_in[4];
    const float* r1   = (const float*)d_in[5];
    const float* b1   = (const float*)d_in[6];
    const float* W2   = (const float*)d_in[7];
    const float* r2   = (const float*)d_in[8];
    const float* b2   = (const float*)d_in[9];
    float* out = (float*)d_out;

    constexpr int CAP = 6144;
    constexpr int SMEM_L1 = (128*(DD+4) + 128*(DD+4)) * 4 + (2*128*RR + CAP) * 4; // 167936
    constexpr int SMEM_L2 = (128*(DD+4) +  64*(DD+4)) * 4 + (2*128*RR + CAP) * 4; // 134144
    cudaFuncSetAttribute(k_layer<128,false>, cudaFuncAttributeMaxDynamicSharedMemorySize, SMEM_L1);
    cudaFuncSetAttribute(k_layer< 64,true >, cudaFuncAttributeMaxDynamicSharedMemorySize, SMEM_L2);

    void* p = nullptr;
    cudaGetSymbolAddress(&p, g_h);   float* h   = (float*)p;
    cudaGetSymbolAddress(&p, g_Wt1); float* wt1 = (float*)p;
    cudaGetSymbolAddress(&p, g_Wt2); float* wt2 = (float*)p;

    k_zero   <<<(NRSEG+255)/256, 256>>>();
    k_hist   <<<(NE+255)/256,    256>>>(edst, etyp);
    k_scan1  <<<NBLK,           1024>>>();
    k_scan2  <<<1,               512>>>();
    k_scan3  <<<(NRSEG+255)/256, 256>>>();
    k_scatter<<<(NE+255)/256,    256>>>(esrc, edst, etyp);

    k_transpose<<<((RR+1)*128*DD + 255)/256, 256>>>(W1, r1, wt1, 128);
    k_transpose<<<((RR+1)* 64*DD + 255)/256, 256>>>(W2, r2, wt2,  64);

    k_layer<128,false><<<(NN+127)/128, 256, SMEM_L1>>>(x, wt1, b1, h);
    k_layer< 64,true ><<<(NN+127)/128, 256, SMEM_L2>>>(h, wt2, b2, out);
}